// round 4
// baseline (speedup 1.0000x reference)
#include <cuda_runtime.h>
#include <cstdint>

// VectorQuantizer: ze [N,64] f32, codebook [512,64] f32.
// Out (f32): [ zq (N*64) | emb_ix as float (N) | vq_loss (1) ]  (segments
// beyond zq written only if out_size is large enough).
//
// Strategy: fp32 distance GEMM with packed fma.rn.f32x2 (2 FMAs/lane/cyc).
//  - per CTA: 128 tokens, full 512x64 codebook in smem (transposed [d][k],
//    XOR-swizzled to kill LDS bank conflicts), ze tile duplicated per float
//    ([d][2t]=[2t+1]) so both MMA operands are straight LDS.128, no packing.
//  - thread tile: 8 tokens x 16 codes (8 f32x2 code-pairs) = 64 FMA2/d-step.
//  - score = ||e_k||^2 - 2*dot  (||z||^2 irrelevant for argmin).
//  - argmin: ascending scan, strict <, shfl reduce over 16 code-threads with
//    lowest-index tiebreak (matches jnp.argmin first-min semantics).
//  - epilogue: gather winning row from gmem -> zq, exact fp32 loss partials
//    per CTA -> deterministic tree reduce in a tiny finalize kernel.

#define NTHREADS 256
#define TOK_PER_CTA 128
#define DDIM 64
#define KCODES 512

// smem byte layout
#define EMB_BYTES   131072              // 64 rows * 2048B (512 codes * 4B)
#define ZED_OFF     131072              // 64 rows * 1024B (128 tokens * 8B dup)
#define NORM_OFF    196608              // 512 floats
#define WSUM_OFF    198656              // 8 floats
#define SMEM_TOTAL  198688

__device__ float g_partial[8192];

__device__ __forceinline__ void fma2(unsigned long long &d,
                                     unsigned long long a,
                                     unsigned long long b) {
    asm("fma.rn.f32x2 %0, %1, %2, %0;" : "+l"(d) : "l"(a), "l"(b));
}
__device__ __forceinline__ float lo32(unsigned long long x) {
    return __uint_as_float((unsigned)x);
}
__device__ __forceinline__ float hi32(unsigned long long x) {
    return __uint_as_float((unsigned)(x >> 32));
}

extern "C" __global__ void __launch_bounds__(NTHREADS, 1)
vq_main(const float* __restrict__ ze, const float* __restrict__ emb,
        float* __restrict__ zq, float* __restrict__ idxo, int n)
{
    extern __shared__ __align__(1024) char smem[];
    char*  emb_b  = smem;
    char*  zed_b  = smem + ZED_OFF;
    float* norm_s = (float*)(smem + NORM_OFF);
    float* wsum   = (float*)(smem + WSUM_OFF);

    const int tid   = threadIdx.x;
    const int gtok0 = blockIdx.x * TOK_PER_CTA;

    // ---------------- load codebook: transposed [d][k], swizzled; norms ----
    for (int k = tid; k < KCODES; k += NTHREADS) {
        const float4* src = (const float4*)(emb + (size_t)k * DDIM);
        unsigned co = ((unsigned)(k * 4)) ^ ((((unsigned)k >> 5) & 7u) << 4);
        char* dstb = emb_b + co;
        float nrm = 0.f;
        #pragma unroll
        for (int i = 0; i < 16; i++) {
            float4 v = src[i];
            nrm += v.x * v.x + v.y * v.y + v.z * v.z + v.w * v.w;
            int d = 4 * i;
            *(float*)(dstb + (d + 0) * 2048) = v.x;
            *(float*)(dstb + (d + 1) * 2048) = v.y;
            *(float*)(dstb + (d + 2) * 2048) = v.z;
            *(float*)(dstb + (d + 3) * 2048) = v.w;
        }
        norm_s[k] = nrm;
    }

    // ---------------- load ze tile: transposed + duplicated [d][2t] --------
    {
        int t    = tid >> 1;            // token within CTA (2 threads/token)
        int half = (tid & 1) * 32;      // dim half
        int gt   = gtok0 + t; if (gt > n - 1) gt = n - 1;
        const float4* src = (const float4*)(ze + (size_t)gt * DDIM + half);
        #pragma unroll
        for (int i = 0; i < 8; i++) {
            float4 v = src[i];
            int d = half + 4 * i;
            *(float2*)(zed_b + (d + 0) * 1024 + t * 8) = make_float2(v.x, v.x);
            *(float2*)(zed_b + (d + 1) * 1024 + t * 8) = make_float2(v.y, v.y);
            *(float2*)(zed_b + (d + 2) * 1024 + t * 8) = make_float2(v.z, v.z);
            *(float2*)(zed_b + (d + 3) * 1024 + t * 8) = make_float2(v.w, v.w);
        }
    }
    __syncthreads();

    const int tcol = tid & 15;   // code group
    const int trow = tid >> 4;   // token group (8 tokens)

    float minv[8];
    int   mini[8];
    #pragma unroll
    for (int i = 0; i < 8; i++) { minv[i] = 3.402823e38f; mini[i] = 0; }

    const char* abase = zed_b + trow * 64;

    #pragma unroll 1
    for (int ktile = 0; ktile < 2; ktile++) {
        unsigned lbase = (unsigned)(ktile * 1024 + tcol * 64);
        unsigned sv    = (lbase >> 7) & 7u;
        const char* bp0 = emb_b + ((lbase +  0u) ^ (sv << 4));
        const char* bp1 = emb_b + ((lbase + 16u) ^ (sv << 4));
        const char* bp2 = emb_b + ((lbase + 32u) ^ (sv << 4));
        const char* bp3 = emb_b + ((lbase + 48u) ^ (sv << 4));

        unsigned long long acc[8][8];
        #pragma unroll
        for (int i = 0; i < 8; i++)
            #pragma unroll
            for (int j = 0; j < 8; j++) acc[i][j] = 0ull;

        #pragma unroll 4
        for (int d = 0; d < 64; d++) {
            unsigned long long bb[8];
            {
                ulonglong2 x;
                x = *(const ulonglong2*)(bp0 + d * 2048); bb[0] = x.x; bb[1] = x.y;
                x = *(const ulonglong2*)(bp1 + d * 2048); bb[2] = x.x; bb[3] = x.y;
                x = *(const ulonglong2*)(bp2 + d * 2048); bb[4] = x.x; bb[5] = x.y;
                x = *(const ulonglong2*)(bp3 + d * 2048); bb[6] = x.x; bb[7] = x.y;
            }
            unsigned long long aa[8];
            {
                ulonglong2 x;
                x = *(const ulonglong2*)(abase + d * 1024 +  0); aa[0] = x.x; aa[1] = x.y;
                x = *(const ulonglong2*)(abase + d * 1024 + 16); aa[2] = x.x; aa[3] = x.y;
                x = *(const ulonglong2*)(abase + d * 1024 + 32); aa[4] = x.x; aa[5] = x.y;
                x = *(const ulonglong2*)(abase + d * 1024 + 48); aa[6] = x.x; aa[7] = x.y;
            }
            #pragma unroll
            for (int i = 0; i < 8; i++)
                #pragma unroll
                for (int j = 0; j < 8; j++)
                    fma2(acc[i][j], aa[i], bb[j]);
        }

        // score + running argmin (ascending code order; strict < => first min)
        int kc0 = ktile * 256 + tcol * 16;
        #pragma unroll
        for (int j = 0; j < 8; j++) {
            float n0 = norm_s[kc0 + 2 * j];
            float n1 = norm_s[kc0 + 2 * j + 1];
            #pragma unroll
            for (int i = 0; i < 8; i++) {
                float s0 = fmaf(-2.f, lo32(acc[i][j]), n0);
                float s1 = fmaf(-2.f, hi32(acc[i][j]), n1);
                if (s0 < minv[i]) { minv[i] = s0; mini[i] = kc0 + 2 * j; }
                if (s1 < minv[i]) { minv[i] = s1; mini[i] = kc0 + 2 * j + 1; }
            }
        }
    }

    // all warps done with norm_s before we repurpose it for indices
    __syncthreads();
    int* ind_s = (int*)norm_s;   // 128 ints

    // reduce (val, idx) across the 16 code-threads (same half-warp), lowest
    // index wins ties; lane tcol==0 holds the result.
    #pragma unroll
    for (int i = 0; i < 8; i++) {
        float v  = minv[i];
        int   ix = mini[i];
        #pragma unroll
        for (int off = 8; off > 0; off >>= 1) {
            float ov = __shfl_down_sync(0xffffffffu, v,  off, 16);
            int   oi = __shfl_down_sync(0xffffffffu, ix, off, 16);
            if (ov < v || (ov == v && oi < ix)) { v = ov; ix = oi; }
        }
        if (tcol == 0) ind_s[trow * 8 + i] = ix;
    }
    __syncthreads();

    // ---------------- epilogue: gather zq, index, exact loss partial -------
    int ltok   = trow * 8 + (tcol >> 1);
    int gtok   = gtok0 + ltok;
    int dstart = (tcol & 1) * 32;
    float lsum = 0.f;
    if (gtok < n) {
        int kb = ind_s[ltok];
        if ((tcol & 1) == 0 && idxo) idxo[gtok] = (float)kb;
        const float4* es  = (const float4*)(emb + (size_t)kb * DDIM + dstart);
        float4*       dst = (float4*)(zq + (size_t)gtok * DDIM + dstart);
        #pragma unroll
        for (int i = 0; i < 8; i++) {
            float4 e4 = es[i];
            int d = dstart + 4 * i;
            float z0 = *(const float*)(zed_b + (d + 0) * 1024 + ltok * 8);
            float z1 = *(const float*)(zed_b + (d + 1) * 1024 + ltok * 8);
            float z2 = *(const float*)(zed_b + (d + 2) * 1024 + ltok * 8);
            float z3 = *(const float*)(zed_b + (d + 3) * 1024 + ltok * 8);
            float q0 = e4.x - z0, q1 = e4.y - z1, q2 = e4.z - z2, q3 = e4.w - z3;
            lsum += q0 * q0 + q1 * q1 + q2 * q2 + q3 * q3;
            dst[i] = e4;
        }
    }
    #pragma unroll
    for (int off = 16; off > 0; off >>= 1)
        lsum += __shfl_xor_sync(0xffffffffu, lsum, off);
    if ((tid & 31) == 0) wsum[tid >> 5] = lsum;
    __syncthreads();
    if (tid == 0) {
        float s = 0.f;
        #pragma unroll
        for (int i = 0; i < 8; i++) s += wsum[i];
        g_partial[blockIdx.x] = s;
    }
}

extern "C" __global__ void vq_finalize(float* __restrict__ loss_out,
                                       int nparts, float scale)
{
    __shared__ float sh[256];
    float s = 0.f;
    for (int i = threadIdx.x; i < nparts; i += 256) s += g_partial[i];
    sh[threadIdx.x] = s;
    __syncthreads();
    #pragma unroll
    for (int off = 128; off > 0; off >>= 1) {
        if (threadIdx.x < off) sh[threadIdx.x] += sh[threadIdx.x + off];
        __syncthreads();
    }
    if (threadIdx.x == 0) *loss_out = sh[0] * scale;
}

extern "C" void kernel_launch(void* const* d_in, const int* in_sizes, int n_in,
                              void* d_out, int out_size)
{
    const float* ze  = (const float*)d_in[0];
    const float* emb = (const float*)d_in[1];
    int n = in_sizes[0] / DDIM;           // 524288
    float* out = (float*)d_out;

    long long nd = (long long)n * DDIM;
    float* idxo  = ((long long)out_size >= nd + n)     ? out + nd     : nullptr;
    float* losso = ((long long)out_size >= nd + n + 1) ? out + nd + n : nullptr;

    int grid = (n + TOK_PER_CTA - 1) / TOK_PER_CTA;   // 4096

    cudaFuncSetAttribute((const void*)vq_main,
                         cudaFuncAttributeMaxDynamicSharedMemorySize,
                         SMEM_TOTAL);
    vq_main<<<grid, NTHREADS, SMEM_TOTAL>>>(ze, emb, out, idxo, n);
    if (losso)
        vq_finalize<<<1, 256>>>(losso, grid, 2.0f / (float)nd);
}

// round 12
// speedup vs baseline: 1.1460x; 1.1460x over previous
#include <cuda_runtime.h>
#include <cstdint>

// VectorQuantizer via legacy mma.sync tf32 GEMM (+ exact fp32 candidate rescore).
// Out (f32): [ zq (N*64) | emb_ix as float (N) | vq_loss (1) ].

#define DDIM 64
#define KCODES 512
#define TPT 64                 // tokens per tile
#define TILES_PER_CTA 8
#define NTHREADS 256
#define MARGIN 1.5f
#define ROWF 68                // padded row length in floats (bank-conflict-free)

// ---- smem byte offsets ------------------------------------------------------
#define ZEP_OFF    0           // 64 * 68 * 4      = 17408
#define BP_OFF     17408       // 512 * 68 * 4     = 139264
#define NORM_OFF   156672      // 512 f32
#define PV_OFF     158720      // 4 * 64 f32
#define VTOK_OFF   159744      // 64 f32
#define TOKMIN_OFF 160000      // 64 u64
#define PAIR_OFF   160512      // 8192 u32 (worst-case capacity)
#define CNT_OFF    193280      // i32
#define WSUM_OFF   193284      // 8 f32
#define SMEM_TOTAL 193344

__device__ float g_partial[8192];

__device__ __forceinline__ void mma_tf32(float* c, const uint32_t a[4],
                                         uint32_t b0, uint32_t b1) {
    asm volatile(
        "mma.sync.aligned.m16n8k8.row.col.f32.tf32.tf32.f32 "
        "{%0,%1,%2,%3}, {%4,%5,%6,%7}, {%8,%9}, {%0,%1,%2,%3};"
        : "+f"(c[0]), "+f"(c[1]), "+f"(c[2]), "+f"(c[3])
        : "r"(a[0]), "r"(a[1]), "r"(a[2]), "r"(a[3]), "r"(b0), "r"(b1));
}

extern "C" __global__ void __launch_bounds__(NTHREADS, 1)
vq_main(const float* __restrict__ ze, const float* __restrict__ emb,
        float* __restrict__ zq, float* __restrict__ idxo, int n)
{
    extern __shared__ __align__(16) char smem[];
    float*    zep    = (float*)(smem + ZEP_OFF);
    float*    bp     = (float*)(smem + BP_OFF);
    float*    norm_s = (float*)(smem + NORM_OFF);
    float*    pv     = (float*)(smem + PV_OFF);
    float*    vtok   = (float*)(smem + VTOK_OFF);
    unsigned long long* tokmin = (unsigned long long*)(smem + TOKMIN_OFF);
    unsigned* pair   = (unsigned*)(smem + PAIR_OFF);
    int*      cnt    = (int*)(smem + CNT_OFF);
    float*    wsum   = (float*)(smem + WSUM_OFF);

    const int tid  = threadIdx.x;
    const int w    = tid >> 5, lane = tid & 31;
    const int g    = lane >> 2, tig = lane & 3;
    const int mg   = w >> 2,   cg  = w & 3;

    // ---- codebook -> SMEM (once per CTA), flat coalesced, NO row spill -----
    {
        const float4* src = (const float4*)emb;
        #pragma unroll 4
        for (int i = tid; i < KCODES * 16; i += NTHREADS) {
            int k = i >> 4, seg = i & 15;
            *(float4*)(bp + k * ROWF + seg * 4) = src[i];
        }
    }
    __syncthreads();
    // exact fp32 norms (sequential accumulation per code)
    for (int k = tid; k < KCODES; k += NTHREADS) {
        const float4* row = (const float4*)(bp + k * ROWF);
        float s = 0.f;
        #pragma unroll
        for (int i = 0; i < 16; i++) {
            float4 v = row[i];
            s += v.x * v.x + v.y * v.y + v.z * v.z + v.w * v.w;
        }
        norm_s[k] = s;
    }

    float lsum = 0.f;

    for (int t = 0; t < TILES_PER_CTA; t++) {
        const int gtok0 = (blockIdx.x * TILES_PER_CTA + t) * TPT;

        // ---- ze tile -> SMEM: warp w owns tokens w*8..w*8+7 ----
        #pragma unroll
        for (int r = 0; r < 8; r++) {
            int tok = w * 8 + r;
            int gt  = gtok0 + tok; if (gt > n - 1) gt = n - 1;
            float2 v = *(const float2*)(ze + (size_t)gt * DDIM + lane * 2);
            *(float2*)(zep + tok * ROWF + lane * 2) = v;
        }
        if (tid < TPT) tokmin[tid] = ~0ull;
        if (tid == 0)  *cnt = 0;
        __syncthreads();

        // ---- mma: warp tile m32 (tokens mg*32..) x n128 (codes cg*128..) ----
        float acc[2][16][4];
        #pragma unroll
        for (int mt = 0; mt < 2; mt++)
            #pragma unroll
            for (int nt = 0; nt < 16; nt++)
                #pragma unroll
                for (int c = 0; c < 4; c++) acc[mt][nt][c] = 0.f;

        const float* za = zep + (mg * 32 + g) * ROWF + tig;
        const float* ba = bp  + (cg * 128 + g) * ROWF + tig;

        #pragma unroll
        for (int kt = 0; kt < 8; kt++) {
            uint32_t a[2][4];
            #pragma unroll
            for (int mt = 0; mt < 2; mt++) {
                const float* p = za + mt * 16 * ROWF + kt * 8;
                a[mt][0] = __float_as_uint(p[0]);
                a[mt][1] = __float_as_uint(p[8 * ROWF]);
                a[mt][2] = __float_as_uint(p[4]);
                a[mt][3] = __float_as_uint(p[8 * ROWF + 4]);
            }
            #pragma unroll
            for (int nt = 0; nt < 16; nt++) {
                const float* q = ba + nt * 8 * ROWF + kt * 8;
                uint32_t b0 = __float_as_uint(q[0]);
                uint32_t b1 = __float_as_uint(q[4]);
                mma_tf32(acc[0][nt], a[0], b0, b1);
                mma_tf32(acc[1][nt], a[1], b0, b1);
            }
        }

        // ---- epilogue A: per-row tf32 min ----
        float2 nrm[16];
        #pragma unroll
        for (int nt = 0; nt < 16; nt++)
            nrm[nt] = *(const float2*)(norm_s + cg * 128 + nt * 8 + tig * 2);

        float v[2][2];
        v[0][0] = v[0][1] = v[1][0] = v[1][1] = 3.402823e38f;
        #pragma unroll
        for (int mt = 0; mt < 2; mt++)
            #pragma unroll
            for (int nt = 0; nt < 16; nt++) {
                float s0 = fmaf(-2.f, acc[mt][nt][0], nrm[nt].x);
                float s1 = fmaf(-2.f, acc[mt][nt][1], nrm[nt].y);
                float s2 = fmaf(-2.f, acc[mt][nt][2], nrm[nt].x);
                float s3 = fmaf(-2.f, acc[mt][nt][3], nrm[nt].y);
                v[mt][0] = fminf(v[mt][0], fminf(s0, s1));
                v[mt][1] = fminf(v[mt][1], fminf(s2, s3));
            }
        #pragma unroll
        for (int mt = 0; mt < 2; mt++)
            #pragma unroll
            for (int h = 0; h < 2; h++) {
                float x = v[mt][h];
                x = fminf(x, __shfl_xor_sync(0xffffffffu, x, 1));
                x = fminf(x, __shfl_xor_sync(0xffffffffu, x, 2));
                v[mt][h] = x;
            }
        if (tig == 0) {
            #pragma unroll
            for (int mt = 0; mt < 2; mt++)
                #pragma unroll
                for (int h = 0; h < 2; h++)
                    pv[cg * 64 + mg * 32 + mt * 16 + h * 8 + g] = v[mt][h];
        }
        __syncthreads();
        if (tid < TPT) {
            float m0 = fminf(pv[tid],       pv[64  + tid]);
            float m1 = fminf(pv[128 + tid], pv[192 + tid]);
            vtok[tid] = fminf(m0, m1) + MARGIN;
        }
        __syncthreads();

        // ---- epilogue B: emit candidate (token,code) pairs ----
        float th[2][2];
        #pragma unroll
        for (int mt = 0; mt < 2; mt++)
            #pragma unroll
            for (int h = 0; h < 2; h++)
                th[mt][h] = vtok[mg * 32 + mt * 16 + h * 8 + g];

        #pragma unroll
        for (int mt = 0; mt < 2; mt++)
            #pragma unroll
            for (int nt = 0; nt < 16; nt++) {
                float s[4];
                s[0] = fmaf(-2.f, acc[mt][nt][0], nrm[nt].x);
                s[1] = fmaf(-2.f, acc[mt][nt][1], nrm[nt].y);
                s[2] = fmaf(-2.f, acc[mt][nt][2], nrm[nt].x);
                s[3] = fmaf(-2.f, acc[mt][nt][3], nrm[nt].y);
                bool any = (fminf(s[0], s[1]) < th[mt][0]) ||
                           (fminf(s[2], s[3]) < th[mt][1]);
                unsigned ma = __ballot_sync(0xffffffffu, any);
                if (ma) {
                    #pragma unroll
                    for (int c = 0; c < 4; c++) {
                        bool p = s[c] < th[mt][c >> 1];
                        unsigned m = __ballot_sync(0xffffffffu, p);
                        if (m) {
                            int leader = __ffs(m) - 1;
                            int base = 0;
                            if (lane == leader) base = atomicAdd(cnt, __popc(m));
                            base = __shfl_sync(0xffffffffu, base, leader);
                            if (p) {
                                int r    = __popc(m & ((1u << lane) - 1));
                                int tok  = mg * 32 + mt * 16 + (c >> 1) * 8 + g;
                                int code = cg * 128 + nt * 8 + tig * 2 + (c & 1);
                                pair[base + r] = (unsigned)((tok << 9) | code);
                            }
                        }
                    }
                }
            }
        __syncthreads();

        // ---- exact fp32 rescore of candidates (warp per pair) ----
        {
            int np = *cnt;
            for (int p = w; p < np; p += 8) {
                unsigned pc = pair[p];
                int tok = pc >> 9, code = pc & 511;
                float2 zz = *(const float2*)(zep + tok  * ROWF + lane * 2);
                float2 ee = *(const float2*)(bp  + code * ROWF + lane * 2);
                float d = zz.x * ee.x + zz.y * ee.y;
                #pragma unroll
                for (int o = 16; o > 0; o >>= 1)
                    d += __shfl_xor_sync(0xffffffffu, d, o);
                if (lane == 0) {
                    float s = fmaf(-2.f, d, norm_s[code]);
                    unsigned u = __float_as_uint(s);
                    u = (u & 0x80000000u) ? ~u : (u | 0x80000000u);
                    unsigned long long enc =
                        ((unsigned long long)u << 32) | (unsigned)code;
                    atomicMin(&tokmin[tok], enc);
                }
            }
        }
        __syncthreads();

        // ---- outputs: zq gather (from SMEM), index, loss partial ----
        {
            int tok  = tid >> 2;
            int qd   = (tid & 3) * 16;
            int gtok = gtok0 + tok;
            if (gtok < n) {
                int code = (int)(tokmin[tok] & 511ull);
                if ((tid & 3) == 0 && idxo) idxo[gtok] = (float)code;
                const float4* es  = (const float4*)(bp  + code * ROWF + qd);
                const float4* zs  = (const float4*)(zep + tok  * ROWF + qd);
                float4*       dst = (float4*)(zq + (size_t)gtok * DDIM + qd);
                #pragma unroll
                for (int i = 0; i < 4; i++) {
                    float4 e4 = es[i], z4 = zs[i];
                    float q0 = e4.x - z4.x, q1 = e4.y - z4.y;
                    float q2 = e4.z - z4.z, q3 = e4.w - z4.w;
                    lsum += q0 * q0 + q1 * q1 + q2 * q2 + q3 * q3;
                    dst[i] = e4;
                }
            }
        }
        __syncthreads();   // before next tile overwrites zep/tokmin
    }

    // ---- per-CTA loss partial ----
    #pragma unroll
    for (int o = 16; o > 0; o >>= 1)
        lsum += __shfl_xor_sync(0xffffffffu, lsum, o);
    if (lane == 0) wsum[w] = lsum;
    __syncthreads();
    if (tid == 0) {
        float s = 0.f;
        #pragma unroll
        for (int i = 0; i < 8; i++) s += wsum[i];
        g_partial[blockIdx.x] = s;
    }
}

extern "C" __global__ void vq_finalize(float* __restrict__ loss_out,
                                       int nparts, float scale)
{
    __shared__ float sh[256];
    float s = 0.f;
    for (int i = threadIdx.x; i < nparts; i += 256) s += g_partial[i];
    sh[threadIdx.x] = s;
    __syncthreads();
    #pragma unroll
    for (int off = 128; off > 0; off >>= 1) {
        if (threadIdx.x < off) sh[threadIdx.x] += sh[threadIdx.x + off];
        __syncthreads();
    }
    if (threadIdx.x == 0) *loss_out = sh[0] * scale;
}

extern "C" void kernel_launch(void* const* d_in, const int* in_sizes, int n_in,
                              void* d_out, int out_size)
{
    const float* ze  = (const float*)d_in[0];
    const float* emb = (const float*)d_in[1];
    int n = in_sizes[0] / DDIM;           // 524288
    float* out = (float*)d_out;

    long long nd = (long long)n * DDIM;
    float* idxo  = ((long long)out_size >= nd + n)     ? out + nd     : nullptr;
    float* losso = ((long long)out_size >= nd + n + 1) ? out + nd + n : nullptr;

    int grid = (n + TPT * TILES_PER_CTA - 1) / (TPT * TILES_PER_CTA);  // 1024

    cudaFuncSetAttribute((const void*)vq_main,
                         cudaFuncAttributeMaxDynamicSharedMemorySize,
                         SMEM_TOTAL);
    vq_main<<<grid, NTHREADS, SMEM_TOTAL>>>(ze, emb, out, idxo, n);
    if (losso)
        vq_finalize<<<1, 256>>>(losso, grid, 2.0f / (float)nd);
}